// round 11
// baseline (speedup 1.0000x reference)
#include <cuda_runtime.h>
#include <cstdint>

#define BATCH 64
#define NI    2048
#define DI    16
#define NO    32
#define DOUT  16

#define KP2   8
#define NPB2  (NI / KP2)    // 256 n per block
#define NPW2  16            // n per warp

__device__ float g_wsum[NI * NO * DI];            // 4 MB  [n][o][i]
__device__ float g_c2[(size_t)NO * NI * BATCH];   // 16 MB [o][n][b]
__device__ float g_part[KP2 * BATCH * 512];       // [kp][b][o*16+d]  1 MB

// ---------------------------------------------------------------------------
__device__ __forceinline__ float tf32r(float v) {
    unsigned r; asm("cvt.rna.tf32.f32 %0, %1;" : "=r"(r) : "f"(v));
    return __uint_as_float(r);
}
__device__ __forceinline__ void mma8(float* d,
                                     float a0, float a1, float a2, float a3,
                                     float b0, float b1) {
    asm volatile(
        "mma.sync.aligned.m16n8k8.row.col.f32.tf32.tf32.f32 "
        "{%0,%1,%2,%3}, {%4,%5,%6,%7}, {%8,%9}, {%0,%1,%2,%3};"
        : "+f"(d[0]), "+f"(d[1]), "+f"(d[2]), "+f"(d[3])
        : "r"(__float_as_uint(a0)), "r"(__float_as_uint(a1)),
          "r"(__float_as_uint(a2)), "r"(__float_as_uint(a3)),
          "r"(__float_as_uint(b0)), "r"(__float_as_uint(b1)));
}

// ============================================================================
// K0: Wsum[n][o][i] = sum_d W[n][o][d][i].
// ============================================================================
__global__ void __launch_bounds__(256)
caps_wsum(const float* __restrict__ Wg) {
    int flat = blockIdx.x * 256 + threadIdx.x;
    int iq = flat & 3;
    int no = flat >> 2;
    const float4* src = (const float4*)(Wg + (size_t)no * 256 + iq * 4);
    float4 s = make_float4(0.f, 0.f, 0.f, 0.f);
#pragma unroll
    for (int d = 0; d < 16; d++) {
        float4 v = __ldg(src + d * 4);
        s.x += v.x; s.y += v.y; s.z += v.z; s.w += v.w;
    }
    *(float4*)(g_wsum + (size_t)no * 16 + iq * 4) = s;
}

// ============================================================================
// K1: routing from Wsum.  grid 1024, block 128 (4 warps), lane = b.
// ============================================================================
__global__ void __launch_bounds__(128)
caps_route2(const float* __restrict__ inp) {
    __shared__ float ws[2][512];
    const int t  = threadIdx.x;
    const int n2 = blockIdx.x;

#pragma unroll
    for (int k = 0; k < 2; k++) {
        const int f   = t + k * 128;
        const int nn2 = f >> 7;
        const int rem = f & 127;
        *(float4*)(&ws[nn2][rem * 4]) =
            *(const float4*)(g_wsum + ((size_t)(2 * n2 + nn2)) * 512 + rem * 4);
    }
    __syncthreads();

    const int wid  = t >> 5;
    const int lane = t & 31;
    const int nn   = wid >> 1;
    const int bh   = wid & 1;
    const int n    = 2 * n2 + nn;
    const int b    = bh * 32 + lane;

    const float4* xr = (const float4*)(inp + ((size_t)b * NI + n) * 16);
    const float4 x0 = __ldg(xr + 0), x1 = __ldg(xr + 1);
    const float4 x2 = __ldg(xr + 2), x3 = __ldg(xr + 3);

    float h[32];
#pragma unroll
    for (int o = 0; o < 32; o++) {
        const float4* wr = (const float4*)(&ws[nn][o * 16]);
        float4 w0 = wr[0], w1 = wr[1], w2 = wr[2], w3 = wr[3];
        float hv = w0.x * x0.x;
        hv = fmaf(w0.y, x0.y, hv); hv = fmaf(w0.z, x0.z, hv); hv = fmaf(w0.w, x0.w, hv);
        hv = fmaf(w1.x, x1.x, hv); hv = fmaf(w1.y, x1.y, hv); hv = fmaf(w1.z, x1.z, hv); hv = fmaf(w1.w, x1.w, hv);
        hv = fmaf(w2.x, x2.x, hv); hv = fmaf(w2.y, x2.y, hv); hv = fmaf(w2.z, x2.z, hv); hv = fmaf(w2.w, x2.w, hv);
        hv = fmaf(w3.x, x3.x, hv); hv = fmaf(w3.y, x3.y, hv); hv = fmaf(w3.z, x3.z, hv); hv = fmaf(w3.w, x3.w, hv);
        h[o] = hv;
    }

    float e1[32], s1 = 0.f;
#pragma unroll
    for (int o = 0; o < 32; o++) {
        e1[o] = __expf(h[o] * 0.03125f);
        s1 += e1[o];
    }
    const float inv1 = __fdividef(1.f, s1);
    float e2[32], s2 = 0.f;
#pragma unroll
    for (int o = 0; o < 32; o++) {
        const float b1 = h[o] * 0.03125f;
        const float b2 = fmaf(e1[o] * inv1, h[o], b1);
        e2[o] = __expf(b2);
        s2 += e2[o];
    }
    const float inv2 = __fdividef(1.f, s2);

#pragma unroll
    for (int o = 0; o < 32; o++)
        g_c2[((size_t)o * NI + n) * BATCH + b] = e2[o] * inv2;
}

// ============================================================================
// K3: mma.sync tf32 contraction, 2 o per block.  grid (8 kp, 16 og).
//   512 threads = 16 warps; warp: n = n0 + w + 16*j (j<16), M=64, N=16 per o.
//   oi processed sequentially per j: x LDG issued once per oi (2nd pass L1-hit),
//   x L2 traffic halved vs 1-o blocks.  acc[2][4][2][4] = 64 regs.
// ============================================================================
#define SRED_STR 1032
#define SMEMC_BYTES (16 * SRED_STR * 4)   // 66048

__global__ __launch_bounds__(512, 1)
void caps_contract(const float* __restrict__ inp, const float* __restrict__ Wg) {
    extern __shared__ float sred[];
    const int t    = threadIdx.x;
    const int w    = t >> 5;
    const int lane = t & 31;
    const int r    = lane >> 2;
    const int c    = lane & 3;
    const int kp   = blockIdx.x;
    const int og   = blockIdx.y;
    const int o0   = og * 2;
    const int n0   = kp * NPB2;

    float acc[2][4][2][4];
#pragma unroll
    for (int oi = 0; oi < 2; oi++)
#pragma unroll
        for (int mt = 0; mt < 4; mt++)
#pragma unroll
            for (int dt = 0; dt < 2; dt++)
#pragma unroll
                for (int q = 0; q < 4; q++) acc[oi][mt][dt][q] = 0.f;

    const float* xb = inp + (size_t)r * (NI * DI) + 4 * c;

    for (int j = 0; j < NPW2; j++) {
        const int n = n0 + w + j * 16;
        const float* xn = xb + (size_t)n * DI;

#pragma unroll
        for (int oi = 0; oi < 2; oi++) {
            const int o = o0 + oi;
            // ---- B fragments (this o) ----
            const float* wbp = Wg + (size_t)n * 8192 + (size_t)o * 256 + r * 16 + c * 4;
            float4 wv0 = __ldg((const float4*)(wbp));
            float4 wv1 = __ldg((const float4*)(wbp + 128));
            float bh[2][2][2], bl[2][2][2];    // [dt][g][slot]
            bh[0][0][0] = tf32r(wv0.x);  bl[0][0][0] = wv0.x - bh[0][0][0];
            bh[0][0][1] = tf32r(wv0.y);  bl[0][0][1] = wv0.y - bh[0][0][1];
            bh[0][1][0] = tf32r(wv0.z);  bl[0][1][0] = wv0.z - bh[0][1][0];
            bh[0][1][1] = tf32r(wv0.w);  bl[0][1][1] = wv0.w - bh[0][1][1];
            bh[1][0][0] = tf32r(wv1.x);  bl[1][0][0] = wv1.x - bh[1][0][0];
            bh[1][0][1] = tf32r(wv1.y);  bl[1][0][1] = wv1.y - bh[1][0][1];
            bh[1][1][0] = tf32r(wv1.z);  bl[1][1][0] = wv1.z - bh[1][1][0];
            bh[1][1][1] = tf32r(wv1.w);  bl[1][1][1] = wv1.w - bh[1][1][1];

            const float* c2n = g_c2 + ((size_t)o * NI + n) * BATCH + r;

#pragma unroll
            for (int mt = 0; mt < 4; mt++) {
                const float c2a = __ldg(c2n + mt * 16);
                const float c2b = __ldg(c2n + mt * 16 + 8);
                const float4 xv0 = __ldg((const float4*)(xn + (size_t)(mt * 16) * (NI * DI)));
                const float4 xv1 = __ldg((const float4*)(xn + (size_t)(mt * 16 + 8) * (NI * DI)));
                const float x0e[4] = {xv0.x, xv0.y, xv0.z, xv0.w};
                const float x1e[4] = {xv1.x, xv1.y, xv1.z, xv1.w};
#pragma unroll
                for (int g = 0; g < 2; g++) {
                    const float y0 = c2a * x0e[2 * g];
                    const float y2 = c2a * x0e[2 * g + 1];
                    const float y1 = c2b * x1e[2 * g];
                    const float y3 = c2b * x1e[2 * g + 1];
                    const float aH0 = tf32r(y0), aH1 = tf32r(y1);
                    const float aH2 = tf32r(y2), aH3 = tf32r(y3);
                    const float aL0 = y0 - aH0, aL1 = y1 - aH1;
                    const float aL2 = y2 - aH2, aL3 = y3 - aH3;
#pragma unroll
                    for (int dt = 0; dt < 2; dt++) {
                        mma8(acc[oi][mt][dt], aH0, aH1, aH2, aH3, bh[dt][g][0], bh[dt][g][1]);
                        mma8(acc[oi][mt][dt], aH0, aH1, aH2, aH3, bl[dt][g][0], bl[dt][g][1]);
                        mma8(acc[oi][mt][dt], aL0, aL1, aL2, aL3, bh[dt][g][0], bh[dt][g][1]);
                    }
                }
            }
        }
    }

    // ---- epilogue: per-o cross-warp reduce -------------------------------
#pragma unroll
    for (int oi = 0; oi < 2; oi++) {
        if (oi) __syncthreads();   // previous reduce done before overwrite
#pragma unroll
        for (int mt = 0; mt < 4; mt++)
#pragma unroll
            for (int dt = 0; dt < 2; dt++) {
                const int base0 = w * SRED_STR + (mt * 16 + r) * 16 + dt * 8 + 2 * c;
                *(float2*)(sred + base0)       = make_float2(acc[oi][mt][dt][0], acc[oi][mt][dt][1]);
                *(float2*)(sred + base0 + 128) = make_float2(acc[oi][mt][dt][2], acc[oi][mt][dt][3]);
            }
        __syncthreads();

#pragma unroll
        for (int rep = 0; rep < 2; rep++) {
            const int v = t + rep * 512;
            float s = 0.f;
#pragma unroll
            for (int k = 0; k < 16; k++) s += sred[k * SRED_STR + v];
            const int b = v >> 4;
            const int d = v & 15;
            g_part[(kp * BATCH + b) * 512 + (o0 + oi) * 16 + d] = s;
        }
    }
}

// ============================================================================
// Finalize: sum 8 kp partials + squash.  grid 64 (b), 512 threads (o*16+d).
// ============================================================================
__global__ void __launch_bounds__(512)
caps_fin(float* __restrict__ out) {
    __shared__ float q[512];
    const int b  = blockIdx.x;
    const int od = threadIdx.x;
    float s = 0.f;
#pragma unroll
    for (int kp = 0; kp < KP2; kp++) s += g_part[(kp * BATCH + b) * 512 + od];
    q[od] = s * s;
    __syncthreads();
    const int o = od >> 4;
    float s2 = 0.f;
#pragma unroll
    for (int k = 0; k < 16; k++) s2 += q[o * 16 + k];
    const float scale = s2 / ((1.f + s2) * sqrtf(s2 + 1e-7f));
    out[(size_t)b * 512 + od] = scale * s;
}

// ============================================================================
extern "C" void kernel_launch(void* const* d_in, const int* in_sizes, int n_in,
                              void* d_out, int out_size) {
    const float* inp;
    const float* Wg;
    if (in_sizes[0] == BATCH * NI * DI) {
        inp = (const float*)d_in[0];
        Wg  = (const float*)d_in[1];
    } else {
        inp = (const float*)d_in[1];
        Wg  = (const float*)d_in[0];
    }

    cudaFuncSetAttribute(caps_contract, cudaFuncAttributeMaxDynamicSharedMemorySize,
                         SMEMC_BYTES);

    caps_wsum<<<1024, 256>>>(Wg);
    caps_route2<<<NI / 2, 128>>>(inp);
    caps_contract<<<dim3(KP2, 16), 512, SMEMC_BYTES>>>(inp, Wg);
    caps_fin<<<BATCH, 512>>>((float*)d_out);
}

// round 12
// speedup vs baseline: 1.1940x; 1.1940x over previous
#include <cuda_runtime.h>
#include <cuda_bf16.h>
#include <cstdint>
#include <cstring>

#define BATCH 64
#define NI    2048
#define DI    16
#define NO    32
#define DOUT  16

#define KP    4
#define NPB   (NI / KP)     // 512 n per block
#define NPW   (NPB / 16)    // 32 n per warp

__device__ float g_wsum[NI * NO * DI];            // 4 MB  [n][o][i]
__device__ float g_c2[(size_t)NO * NI * BATCH];   // 16 MB [o][n][b]
__device__ float g_part[KP * BATCH * 512];        // [kp][b][o*16+d]

// ---------------------------------------------------------------------------
__device__ __forceinline__ unsigned ubf2(__nv_bfloat162 v) {
    unsigned r; memcpy(&r, &v, 4); return r;
}
// pack two bf16 (lo = first k-slot, hi = second)
__device__ __forceinline__ unsigned packh(__nv_bfloat16 lo, __nv_bfloat16 hi) {
    return ubf2(__halves2bfloat162(lo, hi));
}
__device__ __forceinline__ unsigned packf(float lo, float hi) {
    return ubf2(__floats2bfloat162_rn(lo, hi));
}
__device__ __forceinline__ void mma16(float* d,
                                      unsigned a0, unsigned a1, unsigned a2, unsigned a3,
                                      unsigned b0, unsigned b1) {
    asm volatile(
        "mma.sync.aligned.m16n8k16.row.col.f32.bf16.bf16.f32 "
        "{%0,%1,%2,%3}, {%4,%5,%6,%7}, {%8,%9}, {%0,%1,%2,%3};"
        : "+f"(d[0]), "+f"(d[1]), "+f"(d[2]), "+f"(d[3])
        : "r"(a0), "r"(a1), "r"(a2), "r"(a3), "r"(b0), "r"(b1));
}

// ============================================================================
// K0: Wsum[n][o][i] = sum_d W[n][o][d][i].
// ============================================================================
__global__ void __launch_bounds__(256)
caps_wsum(const float* __restrict__ Wg) {
    int flat = blockIdx.x * 256 + threadIdx.x;
    int iq = flat & 3;
    int no = flat >> 2;
    const float4* src = (const float4*)(Wg + (size_t)no * 256 + iq * 4);
    float4 s = make_float4(0.f, 0.f, 0.f, 0.f);
#pragma unroll
    for (int d = 0; d < 16; d++) {
        float4 v = __ldg(src + d * 4);
        s.x += v.x; s.y += v.y; s.z += v.z; s.w += v.w;
    }
    *(float4*)(g_wsum + (size_t)no * 16 + iq * 4) = s;
}

// ============================================================================
// K1: routing from Wsum.  grid 1024, block 128 (4 warps), lane = b.
// ============================================================================
__global__ void __launch_bounds__(128)
caps_route2(const float* __restrict__ inp) {
    __shared__ float ws[2][512];
    const int t  = threadIdx.x;
    const int n2 = blockIdx.x;

#pragma unroll
    for (int k = 0; k < 2; k++) {
        const int f   = t + k * 128;
        const int nn2 = f >> 7;
        const int rem = f & 127;
        *(float4*)(&ws[nn2][rem * 4]) =
            *(const float4*)(g_wsum + ((size_t)(2 * n2 + nn2)) * 512 + rem * 4);
    }
    __syncthreads();

    const int wid  = t >> 5;
    const int lane = t & 31;
    const int nn   = wid >> 1;
    const int bh   = wid & 1;
    const int n    = 2 * n2 + nn;
    const int b    = bh * 32 + lane;

    const float4* xr = (const float4*)(inp + ((size_t)b * NI + n) * 16);
    const float4 x0 = __ldg(xr + 0), x1 = __ldg(xr + 1);
    const float4 x2 = __ldg(xr + 2), x3 = __ldg(xr + 3);

    float h[32];
#pragma unroll
    for (int o = 0; o < 32; o++) {
        const float4* wr = (const float4*)(&ws[nn][o * 16]);
        float4 w0 = wr[0], w1 = wr[1], w2 = wr[2], w3 = wr[3];
        float hv = w0.x * x0.x;
        hv = fmaf(w0.y, x0.y, hv); hv = fmaf(w0.z, x0.z, hv); hv = fmaf(w0.w, x0.w, hv);
        hv = fmaf(w1.x, x1.x, hv); hv = fmaf(w1.y, x1.y, hv); hv = fmaf(w1.z, x1.z, hv); hv = fmaf(w1.w, x1.w, hv);
        hv = fmaf(w2.x, x2.x, hv); hv = fmaf(w2.y, x2.y, hv); hv = fmaf(w2.z, x2.z, hv); hv = fmaf(w2.w, x2.w, hv);
        hv = fmaf(w3.x, x3.x, hv); hv = fmaf(w3.y, x3.y, hv); hv = fmaf(w3.z, x3.z, hv); hv = fmaf(w3.w, x3.w, hv);
        h[o] = hv;
    }

    float e1[32], s1 = 0.f;
#pragma unroll
    for (int o = 0; o < 32; o++) {
        e1[o] = __expf(h[o] * 0.03125f);
        s1 += e1[o];
    }
    const float inv1 = __fdividef(1.f, s1);
    float e2[32], s2 = 0.f;
#pragma unroll
    for (int o = 0; o < 32; o++) {
        const float b1 = h[o] * 0.03125f;
        const float b2 = fmaf(e1[o] * inv1, h[o], b1);
        e2[o] = __expf(b2);
        s2 += e2[o];
    }
    const float inv2 = __fdividef(1.f, s2);

#pragma unroll
    for (int o = 0; o < 32; o++)
        g_c2[((size_t)o * NI + n) * BATCH + b] = e2[o] * inv2;
}

// ============================================================================
// K3: mma.sync bf16 m16n8k16 contraction (split-bf16, 3 terms).
//   grid (4 kp, 32 o), 512 threads = 16 warps.  Warp w: n = n0 + w + 16*j.
//   k-permutation (identical on A and B): mma slot {2c,2c+1,2c+8,2c+9} = i {4c..4c+3}
//   -> all fragment loads are the same float4 pattern as the tf32 version.
//   MMA/warp/n = 24 (vs 48 for tf32 3x).
// ============================================================================
#define SRED_STR 1032
#define SMEMC_BYTES (16 * SRED_STR * 4)   // 66048

__global__ __launch_bounds__(512, 1)
void caps_contract(const float* __restrict__ inp, const float* __restrict__ Wg) {
    extern __shared__ float sred[];
    const int t    = threadIdx.x;
    const int w    = t >> 5;
    const int lane = t & 31;
    const int r    = lane >> 2;
    const int c    = lane & 3;
    const int kp   = blockIdx.x;
    const int o    = blockIdx.y;
    const int n0   = kp * NPB;

    float acc[4][2][4];
#pragma unroll
    for (int mt = 0; mt < 4; mt++)
#pragma unroll
        for (int dt = 0; dt < 2; dt++)
#pragma unroll
            for (int q = 0; q < 4; q++) acc[mt][dt][q] = 0.f;

    const float* xb  = inp + (size_t)r * (NI * DI) + 4 * c;
    const float* c2p = g_c2 + (size_t)o * (NI * BATCH) + r;
    const float* wbp = Wg + (size_t)o * 256 + r * 16 + c * 4;

    for (int j = 0; j < NPW; j++) {
        const int n = n0 + w + j * 16;
        const float* c2n = c2p + (size_t)n * BATCH;
        const float* xn  = xb + (size_t)n * DI;

        // ---- hoisted loads: 2 W + 8 x + 8 c2 ----
        float4 wv[2];
        wv[0] = __ldg((const float4*)(wbp + (size_t)n * 8192));
        wv[1] = __ldg((const float4*)(wbp + (size_t)n * 8192 + 128));
        float4 xv[8];
        float  cva[8];
#pragma unroll
        for (int mt = 0; mt < 4; mt++) {
            cva[2 * mt]     = __ldg(c2n + mt * 16);
            cva[2 * mt + 1] = __ldg(c2n + mt * 16 + 8);
            xv[2 * mt]      = __ldg((const float4*)(xn + (size_t)(mt * 16) * (NI * DI)));
            xv[2 * mt + 1]  = __ldg((const float4*)(xn + (size_t)(mt * 16 + 8) * (NI * DI)));
        }

        // ---- B fragments: hi/lo bf16 ----
        unsigned bhx[2][2], blx[2][2];
#pragma unroll
        for (int dt = 0; dt < 2; dt++) {
            const float4 v = wv[dt];
            __nv_bfloat16 hx = __float2bfloat16(v.x), hy = __float2bfloat16(v.y);
            __nv_bfloat16 hz = __float2bfloat16(v.z), hw = __float2bfloat16(v.w);
            bhx[dt][0] = packh(hx, hy);
            bhx[dt][1] = packh(hz, hw);
            blx[dt][0] = packf(v.x - __bfloat162float(hx), v.y - __bfloat162float(hy));
            blx[dt][1] = packf(v.z - __bfloat162float(hz), v.w - __bfloat162float(hw));
        }

#pragma unroll
        for (int mt = 0; mt < 4; mt++) {
            const float c2a = cva[2 * mt];
            const float c2b = cva[2 * mt + 1];
            const float4 xa = xv[2 * mt];
            const float4 xz = xv[2 * mt + 1];
            const float y0 = c2a * xa.x, y1 = c2a * xa.y, y2 = c2a * xa.z, y3 = c2a * xa.w;
            const float z0 = c2b * xz.x, z1 = c2b * xz.y, z2 = c2b * xz.z, z3 = c2b * xz.w;

            __nv_bfloat16 hy0 = __float2bfloat16(y0), hy1 = __float2bfloat16(y1);
            __nv_bfloat16 hy2 = __float2bfloat16(y2), hy3 = __float2bfloat16(y3);
            __nv_bfloat16 hz0 = __float2bfloat16(z0), hz1 = __float2bfloat16(z1);
            __nv_bfloat16 hz2 = __float2bfloat16(z2), hz3 = __float2bfloat16(z3);

            // a0: row r slots(2c,2c+1)=i(4c,4c+1); a1: row r+8; a2/a3: i(4c+2,4c+3)
            const unsigned aH0 = packh(hy0, hy1);
            const unsigned aH1 = packh(hz0, hz1);
            const unsigned aH2 = packh(hy2, hy3);
            const unsigned aH3 = packh(hz2, hz3);
            const unsigned aL0 = packf(y0 - __bfloat162float(hy0), y1 - __bfloat162float(hy1));
            const unsigned aL1 = packf(z0 - __bfloat162float(hz0), z1 - __bfloat162float(hz1));
            const unsigned aL2 = packf(y2 - __bfloat162float(hy2), y3 - __bfloat162float(hy3));
            const unsigned aL3 = packf(z2 - __bfloat162float(hz2), z3 - __bfloat162float(hz3));

#pragma unroll
            for (int dt = 0; dt < 2; dt++) {
                mma16(acc[mt][dt], aH0, aH1, aH2, aH3, bhx[dt][0], bhx[dt][1]);
                mma16(acc[mt][dt], aH0, aH1, aH2, aH3, blx[dt][0], blx[dt][1]);
                mma16(acc[mt][dt], aL0, aL1, aL2, aL3, bhx[dt][0], bhx[dt][1]);
            }
        }
    }

    // ---- epilogue: per-warp partial -> smem, cross-warp reduce -------------
    // D fragment: c0 at (row r, col 2c), c1 col+1, c2 row+8, c3 row+8 col+1.
#pragma unroll
    for (int mt = 0; mt < 4; mt++)
#pragma unroll
        for (int dt = 0; dt < 2; dt++) {
            const int base0 = w * SRED_STR + (mt * 16 + r) * 16 + dt * 8 + 2 * c;
            *(float2*)(sred + base0)       = make_float2(acc[mt][dt][0], acc[mt][dt][1]);
            *(float2*)(sred + base0 + 128) = make_float2(acc[mt][dt][2], acc[mt][dt][3]);
        }
    __syncthreads();

#pragma unroll
    for (int rep = 0; rep < 2; rep++) {
        const int v = t + rep * 512;
        float s = 0.f;
#pragma unroll
        for (int k = 0; k < 16; k++) s += sred[k * SRED_STR + v];
        const int b = v >> 4;
        const int d = v & 15;
        g_part[(kp * BATCH + b) * 512 + o * 16 + d] = s;
    }
}

// ============================================================================
// Finalize: sum 4 kp partials + squash.  grid 64 (b), 512 threads (o*16+d).
// ============================================================================
__global__ void __launch_bounds__(512)
caps_fin(float* __restrict__ out) {
    __shared__ float q[512];
    const int b  = blockIdx.x;
    const int od = threadIdx.x;
    float s = 0.f;
#pragma unroll
    for (int kp = 0; kp < KP; kp++) s += g_part[(kp * BATCH + b) * 512 + od];
    q[od] = s * s;
    __syncthreads();
    const int o = od >> 4;
    float s2 = 0.f;
#pragma unroll
    for (int k = 0; k < 16; k++) s2 += q[o * 16 + k];
    const float scale = s2 / ((1.f + s2) * sqrtf(s2 + 1e-7f));
    out[(size_t)b * 512 + od] = scale * s;
}

// ============================================================================
extern "C" void kernel_launch(void* const* d_in, const int* in_sizes, int n_in,
                              void* d_out, int out_size) {
    const float* inp;
    const float* Wg;
    if (in_sizes[0] == BATCH * NI * DI) {
        inp = (const float*)d_in[0];
        Wg  = (const float*)d_in[1];
    } else {
        inp = (const float*)d_in[1];
        Wg  = (const float*)d_in[0];
    }

    cudaFuncSetAttribute(caps_contract, cudaFuncAttributeMaxDynamicSharedMemorySize,
                         SMEMC_BYTES);

    caps_wsum<<<1024, 256>>>(Wg);
    caps_route2<<<NI / 2, 128>>>(inp);
    caps_contract<<<dim3(KP, NO), 512, SMEMC_BYTES>>>(inp, Wg);
    caps_fin<<<BATCH, 512>>>((float*)d_out);
}